// round 16
// baseline (speedup 1.0000x reference)
#include <cuda_runtime.h>
#include <cuda_bf16.h>

#define N_NODES 50000
#define D 32
#define D4 8

// Scratch (device globals — no allocation allowed).
__device__ float g_seg[N_NODES * D];   // step1 accumulator -> 0.5*(m W^T) (in place)
__device__ float g_deg[N_NODES];       // in-degree
__device__ float g_g[N_NODES * D];     // init b/2, += 0.5*(m W^T)[src]

__device__ __forceinline__ void red_add_v4(float* ptr, float4 v) {
    asm volatile("red.global.add.v4.f32 [%0], {%1, %2, %3, %4};"
                 :: "l"(ptr), "f"(v.x), "f"(v.y), "f"(v.z), "f"(v.w)
                 : "memory");
}

__device__ __forceinline__ float4 ld_cs_v4(const float4* ptr) {
    float4 v;
    asm volatile("ld.global.cs.v4.f32 {%0, %1, %2, %3}, [%4];"
                 : "=f"(v.x), "=f"(v.y), "=f"(v.z), "=f"(v.w) : "l"(ptr));
    return v;
}

__device__ __forceinline__ void st_cs_v4(float4* ptr, float4 v) {
    asm volatile("st.global.cs.v4.f32 [%0], {%1, %2, %3, %4};"
                 :: "l"(ptr), "f"(v.x), "f"(v.y), "f"(v.z), "f"(v.w)
                 : "memory");
}

// ---------------------------------------------------------------------------
// K1: g_seg = 0, deg = 0, g_g rows = b/2 (bias+0.5 folded into init)
// ---------------------------------------------------------------------------
__global__ void k_zero(const float* __restrict__ b) {
    int i = blockIdx.x * blockDim.x + threadIdx.x;   // over N_NODES * D4
    if (i < N_NODES * D4) {
        ((float4*)g_seg)[i] = make_float4(0.f, 0.f, 0.f, 0.f);
        float4 bb = *(const float4*)&b[(i & 7) * 4];
        bb.x *= 0.5f; bb.y *= 0.5f; bb.z *= 0.5f; bb.w *= 0.5f;
        ((float4*)g_g)[i] = bb;
    }
    if (i < N_NODES) g_deg[i] = 0.0f;
}

// ---------------------------------------------------------------------------
// K2: seg[dst] += ef[e]; deg[dst] += 1.  8 threads/edge, ILP=4.
// ALL index loads first, then all value loads, then REDGs (max front MLP).
// ---------------------------------------------------------------------------
__global__ void k_scatter_feats(const float4* __restrict__ ef,
                                const int* __restrict__ dst, int E, int q) {
    int t = blockIdx.x * blockDim.x + threadIdx.x;   // over q * D4
    if (t >= q * D4) return;
    int e0 = t >> 3;
    int d4 = t & 7;
    int e1 = e0 + q, e2 = e0 + 2 * q, e3 = e0 + 3 * q;
    bool p1 = e1 < E, p2 = e2 < E, p3 = e3 < E;

    int n0 = dst[e0];
    int n1 = 0, n2 = 0, n3 = 0;
    if (p1) n1 = dst[e1];
    if (p2) n2 = dst[e2];
    if (p3) n3 = dst[e3];

    float4 v0 = ld_cs_v4(&ef[e0 * D4 + d4]);
    float4 v1, v2, v3;
    if (p1) v1 = ld_cs_v4(&ef[e1 * D4 + d4]);
    if (p2) v2 = ld_cs_v4(&ef[e2 * D4 + d4]);
    if (p3) v3 = ld_cs_v4(&ef[e3 * D4 + d4]);

    red_add_v4(&g_seg[n0 * D + d4 * 4], v0);
    if (p1) red_add_v4(&g_seg[n1 * D + d4 * 4], v1);
    if (p2) red_add_v4(&g_seg[n2 * D + d4 * 4], v2);
    if (p3) red_add_v4(&g_seg[n3 * D + d4 * 4], v3);
    if (d4 == 0) {
        atomicAdd(&g_deg[n0], 1.0f);
        if (p1) atomicAdd(&g_deg[n1], 1.0f);
        if (p2) atomicAdd(&g_deg[n2], 1.0f);
        if (p3) atomicAdd(&g_deg[n3], 1.0f);
    }
}

// ---------------------------------------------------------------------------
// K3: m = seg/max(deg,1); g_seg row <- 0.5 * (m @ W^T)  (warp per node)
// ---------------------------------------------------------------------------
__global__ void k_norm_gemm(const float* __restrict__ W) {
    __shared__ float Ws[D * (D + 1)];
    __shared__ float ms[8][D];
    for (int i = threadIdx.x; i < D * D; i += blockDim.x)
        Ws[(i / D) * (D + 1) + (i % D)] = W[i];
    __syncthreads();

    int w = (blockIdx.x * blockDim.x + threadIdx.x) >> 5;
    if (w >= N_NODES) return;
    int lane = threadIdx.x & 31;
    int wib  = (threadIdx.x >> 5) & 7;

    float inv = 1.0f / fmaxf(g_deg[w], 1.0f);
    ms[wib][lane] = g_seg[w * D + lane] * inv;
    __syncwarp();
    float acc = 0.0f;
#pragma unroll
    for (int k = 0; k < D; k++)
        acc = fmaf(ms[wib][k], Ws[lane * (D + 1) + k], acc);
    g_seg[w * D + lane] = 0.5f * acc;
}

// ---------------------------------------------------------------------------
// K4: g_g[dst] += g_seg[src].  8 threads/edge, ILP=4, fully front-batched.
// (Measured optimum of the ILP curve: 32 regs, occ ~88%, 40.2-40.4 us.)
// ---------------------------------------------------------------------------
__global__ void k_gather_scatter(const int* __restrict__ src,
                                 const int* __restrict__ dst, int E, int q) {
    int t = blockIdx.x * blockDim.x + threadIdx.x;   // over q * D4
    if (t >= q * D4) return;
    int e0 = t >> 3;
    int d4 = t & 7;
    int e1 = e0 + q, e2 = e0 + 2 * q, e3 = e0 + 3 * q;
    bool p1 = e1 < E, p2 = e2 < E, p3 = e3 < E;

    int ns0 = src[e0], nd0 = dst[e0];
    int ns1 = 0, nd1 = 0, ns2 = 0, nd2 = 0, ns3 = 0, nd3 = 0;
    if (p1) { ns1 = src[e1]; nd1 = dst[e1]; }
    if (p2) { ns2 = src[e2]; nd2 = dst[e2]; }
    if (p3) { ns3 = src[e3]; nd3 = dst[e3]; }

    float4 v0 = *(const float4*)&g_seg[ns0 * D + d4 * 4];
    float4 v1, v2, v3;
    if (p1) v1 = *(const float4*)&g_seg[ns1 * D + d4 * 4];
    if (p2) v2 = *(const float4*)&g_seg[ns2 * D + d4 * 4];
    if (p3) v3 = *(const float4*)&g_seg[ns3 * D + d4 * 4];

    red_add_v4(&g_g[nd0 * D + d4 * 4], v0);
    if (p1) red_add_v4(&g_g[nd1 * D + d4 * 4], v1);
    if (p2) red_add_v4(&g_g[nd2 * D + d4 * 4], v2);
    if (p3) red_add_v4(&g_g[nd3 * D + d4 * 4], v3);
}

// ---------------------------------------------------------------------------
// K5: out[e] = g_g[src[e]] + g_g[dst[e]].  8 threads/edge, ILP=4.
// ---------------------------------------------------------------------------
__global__ void k_edge_out(const int* __restrict__ src,
                           const int* __restrict__ dst,
                           float4* __restrict__ out, int E, int q) {
    int t = blockIdx.x * blockDim.x + threadIdx.x;   // over q * D4
    if (t >= q * D4) return;
    int e0 = t >> 3;
    int d4 = t & 7;
    int e1 = e0 + q, e2 = e0 + 2 * q, e3 = e0 + 3 * q;
    bool p1 = e1 < E, p2 = e2 < E, p3 = e3 < E;

    int ns0 = src[e0], nd0 = dst[e0];
    int ns1 = 0, nd1 = 0, ns2 = 0, nd2 = 0, ns3 = 0, nd3 = 0;
    if (p1) { ns1 = src[e1]; nd1 = dst[e1]; }
    if (p2) { ns2 = src[e2]; nd2 = dst[e2]; }
    if (p3) { ns3 = src[e3]; nd3 = dst[e3]; }

    float4 a0 = *(const float4*)&g_g[ns0 * D + d4 * 4];
    float4 c0 = *(const float4*)&g_g[nd0 * D + d4 * 4];
    float4 a1, c1, a2, c2, a3, c3;
    if (p1) { a1 = *(const float4*)&g_g[ns1 * D + d4 * 4];
              c1 = *(const float4*)&g_g[nd1 * D + d4 * 4]; }
    if (p2) { a2 = *(const float4*)&g_g[ns2 * D + d4 * 4];
              c2 = *(const float4*)&g_g[nd2 * D + d4 * 4]; }
    if (p3) { a3 = *(const float4*)&g_g[ns3 * D + d4 * 4];
              c3 = *(const float4*)&g_g[nd3 * D + d4 * 4]; }

    float4 o0 = make_float4(a0.x + c0.x, a0.y + c0.y, a0.z + c0.z, a0.w + c0.w);
    st_cs_v4(&out[e0 * D4 + d4], o0);
    if (p1) {
        float4 o1 = make_float4(a1.x + c1.x, a1.y + c1.y, a1.z + c1.z, a1.w + c1.w);
        st_cs_v4(&out[e1 * D4 + d4], o1);
    }
    if (p2) {
        float4 o2 = make_float4(a2.x + c2.x, a2.y + c2.y, a2.z + c2.z, a2.w + c2.w);
        st_cs_v4(&out[e2 * D4 + d4], o2);
    }
    if (p3) {
        float4 o3 = make_float4(a3.x + c3.x, a3.y + c3.y, a3.z + c3.z, a3.w + c3.w);
        st_cs_v4(&out[e3 * D4 + d4], o3);
    }
}

// ---------------------------------------------------------------------------
// Launch
// ---------------------------------------------------------------------------
extern "C" void kernel_launch(void* const* d_in, const int* in_sizes, int n_in,
                              void* d_out, int out_size) {
    const float* edge_feats = (const float*)d_in[0];
    const int*   src        = (const int*)d_in[1];
    const int*   dst        = (const int*)d_in[2];
    const float* W          = (const float*)d_in[3];
    const float* b          = (const float*)d_in[4];

    const int E   = in_sizes[1];
    const int q4  = (E + 3) / 4;    // ILP4 edge kernels
    const int TPB = 256;

    const int node_v4      = N_NODES * D4;
    const int node_threads = N_NODES * 32;
    const int q_v4         = q4 * D4;

    k_zero<<<(node_v4 + TPB - 1) / TPB, TPB>>>(b);
    k_scatter_feats<<<(q_v4 + TPB - 1) / TPB, TPB>>>(
        (const float4*)edge_feats, dst, E, q4);
    k_norm_gemm<<<(node_threads + TPB - 1) / TPB, TPB>>>(W);
    k_gather_scatter<<<(q_v4 + TPB - 1) / TPB, TPB>>>(src, dst, E, q4);
    k_edge_out<<<(q_v4 + TPB - 1) / TPB, TPB>>>(src, dst, (float4*)d_out, E, q4);
}

// round 17
// speedup vs baseline: 1.0096x; 1.0096x over previous
#include <cuda_runtime.h>
#include <cuda_bf16.h>

#define N_NODES 50000
#define D 32
#define D4 8

// Scratch (device globals — no allocation allowed).
__device__ float g_seg[N_NODES * D];   // step1 accumulator -> 0.5*(m W^T) (in place)
__device__ float g_deg[N_NODES];       // in-degree
__device__ float g_g[N_NODES * D];     // init b/2 (in K3), += 0.5*(m W^T)[src]

__device__ __forceinline__ void red_add_v4(float* ptr, float4 v) {
    asm volatile("red.global.add.v4.f32 [%0], {%1, %2, %3, %4};"
                 :: "l"(ptr), "f"(v.x), "f"(v.y), "f"(v.z), "f"(v.w)
                 : "memory");
}

__device__ __forceinline__ float4 ld_cs_v4(const float4* ptr) {
    float4 v;
    asm volatile("ld.global.cs.v4.f32 {%0, %1, %2, %3}, [%4];"
                 : "=f"(v.x), "=f"(v.y), "=f"(v.z), "=f"(v.w) : "l"(ptr));
    return v;
}

__device__ __forceinline__ void st_cs_v4(float4* ptr, float4 v) {
    asm volatile("st.global.cs.v4.f32 [%0], {%1, %2, %3, %4};"
                 :: "l"(ptr), "f"(v.x), "f"(v.y), "f"(v.z), "f"(v.w)
                 : "memory");
}

// ---------------------------------------------------------------------------
// K1: g_seg = 0, deg = 0.  (g_g init moved into K3.)
// ---------------------------------------------------------------------------
__global__ void k_zero() {
    int i = blockIdx.x * blockDim.x + threadIdx.x;   // over N_NODES * D4 / 2
    int n2 = N_NODES * D4 / 2;
    if (i < n2) {
        ((float4*)g_seg)[i]      = make_float4(0.f, 0.f, 0.f, 0.f);
        ((float4*)g_seg)[i + n2] = make_float4(0.f, 0.f, 0.f, 0.f);
    }
    if (i < N_NODES) g_deg[i] = 0.0f;
}

// ---------------------------------------------------------------------------
// K2: seg[dst] += ef[e]; deg[dst] += 1.  8 threads/edge, ILP=4.
// (Verified-optimal shape — unchanged.)
// ---------------------------------------------------------------------------
__global__ void k_scatter_feats(const float4* __restrict__ ef,
                                const int* __restrict__ dst, int E, int q) {
    int t = blockIdx.x * blockDim.x + threadIdx.x;   // over q * D4
    if (t >= q * D4) return;
    int e0 = t >> 3;
    int d4 = t & 7;
    int e1 = e0 + q, e2 = e0 + 2 * q, e3 = e0 + 3 * q;
    bool p1 = e1 < E, p2 = e2 < E, p3 = e3 < E;

    int n0 = dst[e0];
    int n1 = 0, n2 = 0, n3 = 0;
    if (p1) n1 = dst[e1];
    if (p2) n2 = dst[e2];
    if (p3) n3 = dst[e3];

    float4 v0 = ld_cs_v4(&ef[e0 * D4 + d4]);
    float4 v1, v2, v3;
    if (p1) v1 = ld_cs_v4(&ef[e1 * D4 + d4]);
    if (p2) v2 = ld_cs_v4(&ef[e2 * D4 + d4]);
    if (p3) v3 = ld_cs_v4(&ef[e3 * D4 + d4]);

    red_add_v4(&g_seg[n0 * D + d4 * 4], v0);
    if (p1) red_add_v4(&g_seg[n1 * D + d4 * 4], v1);
    if (p2) red_add_v4(&g_seg[n2 * D + d4 * 4], v2);
    if (p3) red_add_v4(&g_seg[n3 * D + d4 * 4], v3);
    if (d4 == 0) {
        atomicAdd(&g_deg[n0], 1.0f);
        if (p1) atomicAdd(&g_deg[n1], 1.0f);
        if (p2) atomicAdd(&g_deg[n2], 1.0f);
        if (p3) atomicAdd(&g_deg[n3], 1.0f);
    }
}

// ---------------------------------------------------------------------------
// K3: m = seg/max(deg,1); g_seg row <- 0.5 * (m @ W^T); g_g row <- b/2.
// (Warp per node; absorbs the g_g init formerly in K1.)
// ---------------------------------------------------------------------------
__global__ void k_norm_gemm(const float* __restrict__ W,
                            const float* __restrict__ b) {
    __shared__ float Ws[D * (D + 1)];
    __shared__ float ms[8][D];
    for (int i = threadIdx.x; i < D * D; i += blockDim.x)
        Ws[(i / D) * (D + 1) + (i % D)] = W[i];
    __syncthreads();

    int w = (blockIdx.x * blockDim.x + threadIdx.x) >> 5;
    if (w >= N_NODES) return;
    int lane = threadIdx.x & 31;
    int wib  = (threadIdx.x >> 5) & 7;

    float inv = 1.0f / fmaxf(g_deg[w], 1.0f);
    ms[wib][lane] = g_seg[w * D + lane] * inv;
    __syncwarp();
    float acc = 0.0f;
#pragma unroll
    for (int k = 0; k < D; k++)
        acc = fmaf(ms[wib][k], Ws[lane * (D + 1) + k], acc);
    g_seg[w * D + lane] = 0.5f * acc;
    g_g[w * D + lane]   = 0.5f * b[lane];            // bias/2 init (was K1)
}

// ---------------------------------------------------------------------------
// K4: g_g[dst] += g_seg[src].  8 threads/edge, ILP=4, fully front-batched.
// (Verified-optimal shape — unchanged: 32 regs, occ ~88%, 40.2-40.5 us.)
// ---------------------------------------------------------------------------
__global__ void k_gather_scatter(const int* __restrict__ src,
                                 const int* __restrict__ dst, int E, int q) {
    int t = blockIdx.x * blockDim.x + threadIdx.x;   // over q * D4
    if (t >= q * D4) return;
    int e0 = t >> 3;
    int d4 = t & 7;
    int e1 = e0 + q, e2 = e0 + 2 * q, e3 = e0 + 3 * q;
    bool p1 = e1 < E, p2 = e2 < E, p3 = e3 < E;

    int ns0 = src[e0], nd0 = dst[e0];
    int ns1 = 0, nd1 = 0, ns2 = 0, nd2 = 0, ns3 = 0, nd3 = 0;
    if (p1) { ns1 = src[e1]; nd1 = dst[e1]; }
    if (p2) { ns2 = src[e2]; nd2 = dst[e2]; }
    if (p3) { ns3 = src[e3]; nd3 = dst[e3]; }

    float4 v0 = *(const float4*)&g_seg[ns0 * D + d4 * 4];
    float4 v1, v2, v3;
    if (p1) v1 = *(const float4*)&g_seg[ns1 * D + d4 * 4];
    if (p2) v2 = *(const float4*)&g_seg[ns2 * D + d4 * 4];
    if (p3) v3 = *(const float4*)&g_seg[ns3 * D + d4 * 4];

    red_add_v4(&g_g[nd0 * D + d4 * 4], v0);
    if (p1) red_add_v4(&g_g[nd1 * D + d4 * 4], v1);
    if (p2) red_add_v4(&g_g[nd2 * D + d4 * 4], v2);
    if (p3) red_add_v4(&g_g[nd3 * D + d4 * 4], v3);
}

// ---------------------------------------------------------------------------
// K5: out[e] = g_g[src[e]] + g_g[dst[e]].  8 threads/edge, ILP=4.
// (Verified-optimal shape — unchanged.)
// ---------------------------------------------------------------------------
__global__ void k_edge_out(const int* __restrict__ src,
                           const int* __restrict__ dst,
                           float4* __restrict__ out, int E, int q) {
    int t = blockIdx.x * blockDim.x + threadIdx.x;   // over q * D4
    if (t >= q * D4) return;
    int e0 = t >> 3;
    int d4 = t & 7;
    int e1 = e0 + q, e2 = e0 + 2 * q, e3 = e0 + 3 * q;
    bool p1 = e1 < E, p2 = e2 < E, p3 = e3 < E;

    int ns0 = src[e0], nd0 = dst[e0];
    int ns1 = 0, nd1 = 0, ns2 = 0, nd2 = 0, ns3 = 0, nd3 = 0;
    if (p1) { ns1 = src[e1]; nd1 = dst[e1]; }
    if (p2) { ns2 = src[e2]; nd2 = dst[e2]; }
    if (p3) { ns3 = src[e3]; nd3 = dst[e3]; }

    float4 a0 = *(const float4*)&g_g[ns0 * D + d4 * 4];
    float4 c0 = *(const float4*)&g_g[nd0 * D + d4 * 4];
    float4 a1, c1, a2, c2, a3, c3;
    if (p1) { a1 = *(const float4*)&g_g[ns1 * D + d4 * 4];
              c1 = *(const float4*)&g_g[nd1 * D + d4 * 4]; }
    if (p2) { a2 = *(const float4*)&g_g[ns2 * D + d4 * 4];
              c2 = *(const float4*)&g_g[nd2 * D + d4 * 4]; }
    if (p3) { a3 = *(const float4*)&g_g[ns3 * D + d4 * 4];
              c3 = *(const float4*)&g_g[nd3 * D + d4 * 4]; }

    float4 o0 = make_float4(a0.x + c0.x, a0.y + c0.y, a0.z + c0.z, a0.w + c0.w);
    st_cs_v4(&out[e0 * D4 + d4], o0);
    if (p1) {
        float4 o1 = make_float4(a1.x + c1.x, a1.y + c1.y, a1.z + c1.z, a1.w + c1.w);
        st_cs_v4(&out[e1 * D4 + d4], o1);
    }
    if (p2) {
        float4 o2 = make_float4(a2.x + c2.x, a2.y + c2.y, a2.z + c2.z, a2.w + c2.w);
        st_cs_v4(&out[e2 * D4 + d4], o2);
    }
    if (p3) {
        float4 o3 = make_float4(a3.x + c3.x, a3.y + c3.y, a3.z + c3.z, a3.w + c3.w);
        st_cs_v4(&out[e3 * D4 + d4], o3);
    }
}

// ---------------------------------------------------------------------------
// Launch
// ---------------------------------------------------------------------------
extern "C" void kernel_launch(void* const* d_in, const int* in_sizes, int n_in,
                              void* d_out, int out_size) {
    const float* edge_feats = (const float*)d_in[0];
    const int*   src        = (const int*)d_in[1];
    const int*   dst        = (const int*)d_in[2];
    const float* W          = (const float*)d_in[3];
    const float* b          = (const float*)d_in[4];

    const int E   = in_sizes[1];
    const int q4  = (E + 3) / 4;    // ILP4 edge kernels
    const int TPB = 256;

    const int zero_threads = N_NODES * D4 / 2;       // 200K (ILP2 in K1)
    const int node_threads = N_NODES * 32;
    const int q_v4         = q4 * D4;

    k_zero<<<(zero_threads + TPB - 1) / TPB, TPB>>>();
    k_scatter_feats<<<(q_v4 + TPB - 1) / TPB, TPB>>>(
        (const float4*)edge_feats, dst, E, q4);
    k_norm_gemm<<<(node_threads + TPB - 1) / TPB, TPB>>>(W, b);
    k_gather_scatter<<<(q_v4 + TPB - 1) / TPB, TPB>>>(src, dst, E, q4);
    k_edge_out<<<(q_v4 + TPB - 1) / TPB, TPB>>>(src, dst, (float4*)d_out, E, q4);
}